// round 2
// baseline (speedup 1.0000x reference)
#include <cuda_runtime.h>

// ---------------------------------------------------------------------------
// CausalAttention: B=8, N=2048, d_in=d_out=1024, fp32.
//   Q = x Wq ; K = x Wk ; V = x Wv
//   S = Q K^T (causal) ; P = softmax(S/32) ; O = P V
// Scratch lives in __device__ globals (no allocation allowed).
// ---------------------------------------------------------------------------

#define BATCH 8
#define SEQ   2048
#define DIM   1024

#define BM 128
#define BN 128
#define BK 8
#define TM 8
#define TN 8
#define NTHREADS 256

__device__ float g_Q[(size_t)BATCH * SEQ * DIM];
__device__ float g_K[(size_t)BATCH * SEQ * DIM];
__device__ float g_V[(size_t)BATCH * SEQ * DIM];
__device__ float g_S[(size_t)BATCH * SEQ * SEQ];

// ---------------------------------------------------------------------------
// C = A * B   (A: [M,K] row-major, B: [K,N] row-major, C: [M,N] row-major)
// Batched via blockIdx.z with element strides. All dims multiples of tile dims.
// CAUSAL_KLIM: limit k-loop to (block_row+1)*BM (for P*V where P is lower-tri).
// ---------------------------------------------------------------------------
template <bool CAUSAL_KLIM>
__global__ __launch_bounds__(NTHREADS)
void gemm_nn(const float* __restrict__ A, const float* __restrict__ B,
             float* __restrict__ C, int M, int N, int K,
             long strideA, long strideB, long strideC)
{
    __shared__ float As[BK][BM];
    __shared__ float Bs[BK][BN];

    const int b  = blockIdx.z;
    A += (long)b * strideA;
    B += (long)b * strideB;
    C += (long)b * strideC;

    const int bi = blockIdx.y;   // row tile
    const int bj = blockIdx.x;   // col tile
    const int tid = threadIdx.x;
    const int tx = tid & 15;
    const int ty = tid >> 4;

    int kend = K;
    if (CAUSAL_KLIM) kend = min(K, (bi + 1) * BM);

    // load mappings
    const int aRow  = tid >> 1;          // 0..127
    const int aCol4 = (tid & 1) * 4;     // 0 or 4
    const int bRow  = tid >> 5;          // 0..7
    const int bCol4 = (tid & 31) * 4;    // 0..124

    float acc[TM][TN] = {};

    for (int k0 = 0; k0 < kend; k0 += BK) {
        float4 av = *reinterpret_cast<const float4*>(
            A + (long)(bi * BM + aRow) * K + k0 + aCol4);
        As[aCol4 + 0][aRow] = av.x;
        As[aCol4 + 1][aRow] = av.y;
        As[aCol4 + 2][aRow] = av.z;
        As[aCol4 + 3][aRow] = av.w;

        *reinterpret_cast<float4*>(&Bs[bRow][bCol4]) =
            *reinterpret_cast<const float4*>(
                B + (long)(k0 + bRow) * N + bj * BN + bCol4);

        __syncthreads();

        #pragma unroll
        for (int k = 0; k < BK; k++) {
            // float4 fragment loads -> LDS.128, conflict-free in 2 phases
            float4 a0 = *reinterpret_cast<const float4*>(&As[k][ty * TM]);
            float4 a1 = *reinterpret_cast<const float4*>(&As[k][ty * TM + 4]);
            float4 b0 = *reinterpret_cast<const float4*>(&Bs[k][tx * TN]);
            float4 b1 = *reinterpret_cast<const float4*>(&Bs[k][tx * TN + 4]);
            float ra[TM] = {a0.x, a0.y, a0.z, a0.w, a1.x, a1.y, a1.z, a1.w};
            float rb[TN] = {b0.x, b0.y, b0.z, b0.w, b1.x, b1.y, b1.z, b1.w};
            #pragma unroll
            for (int i = 0; i < TM; i++)
                #pragma unroll
                for (int j = 0; j < TN; j++)
                    acc[i][j] += ra[i] * rb[j];
        }
        __syncthreads();
    }

    #pragma unroll
    for (int i = 0; i < TM; i++) {
        const int row = bi * BM + ty * TM + i;
        float* Crow = C + (long)row * N + bj * BN + tx * TN;
        #pragma unroll
        for (int j = 0; j < TN; j += 4) {
            float4 v = make_float4(acc[i][j], acc[i][j+1], acc[i][j+2], acc[i][j+3]);
            *reinterpret_cast<float4*>(Crow + j) = v;
        }
    }
}

// ---------------------------------------------------------------------------
// S = Q * K^T  (Q: [Nq,K] rm, Km: [Nk,K] rm, S: [Nq,Nk] rm), batched.
// Skips tiles entirely above the causal diagonal (softmax never reads them).
// ---------------------------------------------------------------------------
__global__ __launch_bounds__(NTHREADS)
void gemm_nt_causal(const float* __restrict__ Q, const float* __restrict__ Km,
                    float* __restrict__ S, int Nq, int Nk, int K)
{
    const int bi = blockIdx.y;   // query tile (rows)
    const int bj = blockIdx.x;   // key tile (cols)
    if (bj > bi) return;         // tile fully above diagonal -> unused

    __shared__ float As[BK][BM];
    __shared__ float Bs[BK][BN];

    const int b = blockIdx.z;
    Q  += (long)b * Nq * K;
    Km += (long)b * Nk * K;
    S  += (long)b * Nq * Nk;

    const int tid = threadIdx.x;
    const int tx = tid & 15;
    const int ty = tid >> 4;

    const int aRow  = tid >> 1;
    const int aCol4 = (tid & 1) * 4;

    float acc[TM][TN] = {};

    for (int k0 = 0; k0 < K; k0 += BK) {
        float4 av = *reinterpret_cast<const float4*>(
            Q + (long)(bi * BM + aRow) * K + k0 + aCol4);
        As[aCol4 + 0][aRow] = av.x;
        As[aCol4 + 1][aRow] = av.y;
        As[aCol4 + 2][aRow] = av.z;
        As[aCol4 + 3][aRow] = av.w;

        float4 bv = *reinterpret_cast<const float4*>(
            Km + (long)(bj * BN + aRow) * K + k0 + aCol4);
        Bs[aCol4 + 0][aRow] = bv.x;
        Bs[aCol4 + 1][aRow] = bv.y;
        Bs[aCol4 + 2][aRow] = bv.z;
        Bs[aCol4 + 3][aRow] = bv.w;

        __syncthreads();

        #pragma unroll
        for (int k = 0; k < BK; k++) {
            float4 a0 = *reinterpret_cast<const float4*>(&As[k][ty * TM]);
            float4 a1 = *reinterpret_cast<const float4*>(&As[k][ty * TM + 4]);
            float4 b0 = *reinterpret_cast<const float4*>(&Bs[k][tx * TN]);
            float4 b1 = *reinterpret_cast<const float4*>(&Bs[k][tx * TN + 4]);
            float ra[TM] = {a0.x, a0.y, a0.z, a0.w, a1.x, a1.y, a1.z, a1.w};
            float rb[TN] = {b0.x, b0.y, b0.z, b0.w, b1.x, b1.y, b1.z, b1.w};
            #pragma unroll
            for (int i = 0; i < TM; i++)
                #pragma unroll
                for (int j = 0; j < TN; j++)
                    acc[i][j] += ra[i] * rb[j];
        }
        __syncthreads();
    }

    #pragma unroll
    for (int i = 0; i < TM; i++) {
        const int row = bi * BM + ty * TM + i;
        float* Srow = S + (long)row * Nk + bj * BN + tx * TN;
        #pragma unroll
        for (int j = 0; j < TN; j += 4) {
            float4 v = make_float4(acc[i][j], acc[i][j+1], acc[i][j+2], acc[i][j+3]);
            *reinterpret_cast<float4*>(Srow + j) = v;
        }
    }
}

// ---------------------------------------------------------------------------
// Causal softmax in place: row n of batch b, valid entries m in [0, n],
// scale = 1/sqrt(1024) = 1/32, zeros written for m > n.
// ---------------------------------------------------------------------------
__global__ __launch_bounds__(256)
void softmax_causal(float* __restrict__ S, int N)
{
    const int n = blockIdx.x;
    const int b = blockIdx.y;
    float* row = S + ((long)b * N + n) * N;
    const int tid = threadIdx.x;
    const float scale = 0.03125f;   // 1/32

    __shared__ float red[256];

    float m = -3.4e38f;
    for (int j = tid; j <= n; j += 256) m = fmaxf(m, row[j]);
    red[tid] = m;
    __syncthreads();
    for (int s = 128; s > 0; s >>= 1) {
        if (tid < s) red[tid] = fmaxf(red[tid], red[tid + s]);
        __syncthreads();
    }
    const float rowmax = red[0] * scale;
    __syncthreads();

    float sum = 0.f;
    for (int j = tid; j <= n; j += 256) {
        float p = __expf(row[j] * scale - rowmax);
        row[j] = p;
        sum += p;
    }
    red[tid] = sum;
    __syncthreads();
    for (int s = 128; s > 0; s >>= 1) {
        if (tid < s) red[tid] += red[tid + s];
        __syncthreads();
    }
    const float inv = 1.0f / red[0];
    __syncthreads();

    for (int j = tid; j <= n; j += 256) row[j] *= inv;
    for (int j = n + 1 + tid; j < N; j += 256) row[j] = 0.f;
}

// ---------------------------------------------------------------------------
extern "C" void kernel_launch(void* const* d_in, const int* in_sizes, int n_in,
                              void* d_out, int out_size)
{
    const float* x  = (const float*)d_in[0];
    const float* Wq = (const float*)d_in[1];
    const float* Wk = (const float*)d_in[2];
    const float* Wv = (const float*)d_in[3];
    float* out = (float*)d_out;

    float *Q, *Kp, *V, *S;
    cudaGetSymbolAddress((void**)&Q,  g_Q);
    cudaGetSymbolAddress((void**)&Kp, g_K);
    cudaGetSymbolAddress((void**)&V,  g_V);
    cudaGetSymbolAddress((void**)&S,  g_S);

    const dim3 blk(NTHREADS);

    // QKV projections: [16384,1024] x [1024,1024]
    const int M = BATCH * SEQ;          // 16384
    dim3 gq(DIM / BN, M / BM, 1);       // (8, 128)
    gemm_nn<false><<<gq, blk>>>(x, Wq, Q,  M, DIM, DIM, 0, 0, 0);
    gemm_nn<false><<<gq, blk>>>(x, Wk, Kp, M, DIM, DIM, 0, 0, 0);
    gemm_nn<false><<<gq, blk>>>(x, Wv, V,  M, DIM, DIM, 0, 0, 0);

    // S = Q K^T (causal tiles only)
    dim3 gs(SEQ / BN, SEQ / BM, BATCH); // (16, 16, 8)
    gemm_nt_causal<<<gs, blk>>>(Q, Kp, S, SEQ, SEQ, DIM);

    // softmax
    softmax_causal<<<dim3(SEQ, BATCH), 256>>>(S, SEQ);

    // O = P V with causal k-limit
    dim3 go(DIM / BN, SEQ / BM, BATCH); // (8, 16, 8)
    gemm_nn<true><<<go, blk>>>(S, V, out, SEQ, DIM, SEQ,
                               (long)SEQ * SEQ, (long)SEQ * DIM, (long)SEQ * DIM);
}

// round 9
// speedup vs baseline: 2.5598x; 2.5598x over previous
#include <cuda_runtime.h>
#include <cstdint>

// ---------------------------------------------------------------------------
// CausalAttention: B=8, N=2048, d_in=d_out=1024, fp32 in/out.
// All GEMMs on tensor pipe via mma.sync.m16n8k8 tf32 (fp32 accumulate).
//   Q = x Wq ; K = x Wk ; V = x Wv
//   S = Q K^T (causal tiles only) ; P = softmax(S/32) ; O = P V (k-limited)
// ---------------------------------------------------------------------------

#define BATCH 8
#define SEQ   2048
#define DIM   1024

#define BM 128
#define BN 128
#define BK 16
#define PADL 136     // smem row length (floats): bank = (8k + m) % 32 -> conflict-free frags

__device__ float g_Q[(size_t)BATCH * SEQ * DIM];
__device__ float g_K[(size_t)BATCH * SEQ * DIM];
__device__ float g_V[(size_t)BATCH * SEQ * DIM];
__device__ float g_S[(size_t)BATCH * SEQ * SEQ];

__device__ __forceinline__ float to_tf32(float x) {
    float r;
    asm("cvt.rna.tf32.f32 %0, %1;" : "=f"(r) : "f"(x));
    return r;
}

__device__ __forceinline__ void mma_tf32(float c[4], const uint32_t a[4], const uint32_t b[2]) {
    asm volatile(
        "mma.sync.aligned.m16n8k8.row.col.f32.tf32.tf32.f32 "
        "{%0,%1,%2,%3}, {%4,%5,%6,%7}, {%8,%9}, {%0,%1,%2,%3};"
        : "+f"(c[0]), "+f"(c[1]), "+f"(c[2]), "+f"(c[3])
        : "r"(a[0]), "r"(a[1]), "r"(a[2]), "r"(a[3]), "r"(b[0]), "r"(b[1]));
}

// ---------------------------------------------------------------------------
// C[M,N] = A[M,K] * B  where B is [K,N] (TRANS_B=false) or [N,K] (TRANS_B=true,
// i.e. C = A * B^T). Batched via blockIdx.z with element strides.
// CAUSAL_SKIP: skip block tiles with bj > bi (upper triangle).
// CAUSAL_KLIM: limit k loop to (bi+1)*BM (P is lower-triangular).
// ---------------------------------------------------------------------------
template <bool TRANS_B, bool CAUSAL_SKIP, bool CAUSAL_KLIM>
__global__ __launch_bounds__(256)
void gemm_tf32(const float* __restrict__ A, const float* __restrict__ B,
               float* __restrict__ C, int M, int N, int K,
               long sA, long sB, long sC)
{
    const int bi = blockIdx.y;
    const int bj = blockIdx.x;
    if (CAUSAL_SKIP && bj > bi) return;

    __shared__ float As[2][BK][PADL];   // [k][m], padded
    __shared__ float Bs[2][BK][PADL];   // [k][n], padded

    const int b = blockIdx.z;
    A += (long)b * sA;
    B += (long)b * sB;
    C += (long)b * sC;

    const int tid  = threadIdx.x;
    const int lane = tid & 31;
    const int wid  = tid >> 5;
    const int wm = (wid & 1) * 64;    // warp row offset in block tile
    const int wn = (wid >> 1) * 32;   // warp col offset
    const int g  = lane >> 2;         // group id 0..7
    const int tg = lane & 3;          // thread-in-group 0..3

    const int kend = CAUSAL_KLIM ? min(K, (bi + 1) * BM) : K;
    const int T = kend / BK;

    // gmem->reg staging mappings
    const int aRow = tid >> 1;            // 0..127
    const int aK   = (tid & 1) * 8;       // 0 or 8
    const int bK   = tid >> 4;            // 0..15  (nn)
    const int bN   = (tid & 15) * 8;      // 0..120 (nn)
    // nt mode uses aRow/aK-style mapping for B (rows = n index, cols = k)
    const int nRow = tid >> 1;
    const int nK   = (tid & 1) * 8;

    float regA[8], regB[8];
    float acc[4][4][4] = {};

    // ---- gmem load of tile at k0 into registers ----
    auto load_gmem = [&](int k0) {
        const float4 a0 = *reinterpret_cast<const float4*>(
            A + (long)(bi * BM + aRow) * K + k0 + aK);
        const float4 a1 = *reinterpret_cast<const float4*>(
            A + (long)(bi * BM + aRow) * K + k0 + aK + 4);
        regA[0]=a0.x; regA[1]=a0.y; regA[2]=a0.z; regA[3]=a0.w;
        regA[4]=a1.x; regA[5]=a1.y; regA[6]=a1.z; regA[7]=a1.w;
        if (TRANS_B) {
            const float4 b0 = *reinterpret_cast<const float4*>(
                B + (long)(bj * BN + nRow) * K + k0 + nK);
            const float4 b1 = *reinterpret_cast<const float4*>(
                B + (long)(bj * BN + nRow) * K + k0 + nK + 4);
            regB[0]=b0.x; regB[1]=b0.y; regB[2]=b0.z; regB[3]=b0.w;
            regB[4]=b1.x; regB[5]=b1.y; regB[6]=b1.z; regB[7]=b1.w;
        } else {
            const float4 b0 = *reinterpret_cast<const float4*>(
                B + (long)(k0 + bK) * N + bj * BN + bN);
            const float4 b1 = *reinterpret_cast<const float4*>(
                B + (long)(k0 + bK) * N + bj * BN + bN + 4);
            regB[0]=b0.x; regB[1]=b0.y; regB[2]=b0.z; regB[3]=b0.w;
            regB[4]=b1.x; regB[5]=b1.y; regB[6]=b1.z; regB[7]=b1.w;
        }
    };

    // ---- regs -> smem (with tf32 rounding) ----
    auto stage = [&](int buf) {
        #pragma unroll
        for (int i = 0; i < 8; i++)
            As[buf][aK + i][aRow] = to_tf32(regA[i]);
        if (TRANS_B) {
            #pragma unroll
            for (int i = 0; i < 8; i++)
                Bs[buf][nK + i][nRow] = to_tf32(regB[i]);
        } else {
            #pragma unroll
            for (int i = 0; i < 8; i++)
                Bs[buf][bK][bN + i] = to_tf32(regB[i]);
        }
    };

    // ---- mma over one BK=16 smem tile ----
    auto compute = [&](int buf) {
        #pragma unroll
        for (int s = 0; s < 2; s++) {
            uint32_t af[4][4], bf[4][2];
            #pragma unroll
            for (int mt = 0; mt < 4; mt++) {
                const int rb = wm + mt * 16;
                af[mt][0] = __float_as_uint(As[buf][s*8 + tg    ][rb + g    ]);
                af[mt][1] = __float_as_uint(As[buf][s*8 + tg    ][rb + g + 8]);
                af[mt][2] = __float_as_uint(As[buf][s*8 + tg + 4][rb + g    ]);
                af[mt][3] = __float_as_uint(As[buf][s*8 + tg + 4][rb + g + 8]);
            }
            #pragma unroll
            for (int nt = 0; nt < 4; nt++) {
                const int cb = wn + nt * 8;
                bf[nt][0] = __float_as_uint(Bs[buf][s*8 + tg    ][cb + g]);
                bf[nt][1] = __float_as_uint(Bs[buf][s*8 + tg + 4][cb + g]);
            }
            #pragma unroll
            for (int mt = 0; mt < 4; mt++)
                #pragma unroll
                for (int nt = 0; nt < 4; nt++)
                    mma_tf32(acc[mt][nt], af[mt], bf[nt]);
        }
    };

    // ---- pipelined main loop ----
    load_gmem(0);
    stage(0);
    __syncthreads();

    for (int t = 0; t < T; t++) {
        const int cur = t & 1;
        const bool more = (t + 1) < T;
        if (more) load_gmem((t + 1) * BK);
        compute(cur);
        if (more) {
            stage(cur ^ 1);
            __syncthreads();
        }
    }

    // ---- epilogue ----
    #pragma unroll
    for (int mt = 0; mt < 4; mt++) {
        #pragma unroll
        for (int nt = 0; nt < 4; nt++) {
            const int row = bi * BM + wm + mt * 16 + g;
            const int col = bj * BN + wn + nt * 8 + tg * 2;
            float* p = C + (long)row * N + col;
            *reinterpret_cast<float2*>(p) =
                make_float2(acc[mt][nt][0], acc[mt][nt][1]);
            *reinterpret_cast<float2*>(p + 8L * N) =
                make_float2(acc[mt][nt][2], acc[mt][nt][3]);
        }
    }
}

// ---------------------------------------------------------------------------
// Causal softmax in place: row n of batch b, valid entries m in [0, n],
// scale = 1/32, zeros written for m > n.
// ---------------------------------------------------------------------------
__global__ __launch_bounds__(256)
void softmax_causal(float* __restrict__ S, int N)
{
    const int n = blockIdx.x;
    const int b = blockIdx.y;
    float* row = S + ((long)b * N + n) * N;
    const int tid = threadIdx.x;
    const float scale = 0.03125f;   // 1/32

    __shared__ float red[256];

    float m = -3.4e38f;
    for (int j = tid; j <= n; j += 256) m = fmaxf(m, row[j]);
    red[tid] = m;
    __syncthreads();
    for (int s = 128; s > 0; s >>= 1) {
        if (tid < s) red[tid] = fmaxf(red[tid], red[tid + s]);
        __syncthreads();
    }
    const float rowmax = red[0] * scale;
    __syncthreads();

    float sum = 0.f;
    for (int j = tid; j <= n; j += 256) {
        float p = __expf(row[j] * scale - rowmax);
        row[j] = p;
        sum += p;
    }
    red[tid] = sum;
    __syncthreads();
    for (int s = 128; s > 0; s >>= 1) {
        if (tid < s) red[tid] += red[tid + s];
        __syncthreads();
    }
    const float inv = 1.0f / red[0];
    __syncthreads();

    for (int j = tid; j <= n; j += 256) row[j] *= inv;
    for (int j = n + 1 + tid; j < N; j += 256) row[j] = 0.f;
}

// ---------------------------------------------------------------------------
extern "C" void kernel_launch(void* const* d_in, const int* in_sizes, int n_in,
                              void* d_out, int out_size)
{
    const float* x  = (const float*)d_in[0];
    const float* Wq = (const float*)d_in[1];
    const float* Wk = (const float*)d_in[2];
    const float* Wv = (const float*)d_in[3];
    float* out = (float*)d_out;

    float *Q, *Kp, *V, *S;
    cudaGetSymbolAddress((void**)&Q,  g_Q);
    cudaGetSymbolAddress((void**)&Kp, g_K);
    cudaGetSymbolAddress((void**)&V,  g_V);
    cudaGetSymbolAddress((void**)&S,  g_S);

    const dim3 blk(256);
    const int M = BATCH * SEQ;          // 16384

    // QKV projections: [16384,1024] x [1024,1024]
    dim3 gq(DIM / BN, M / BM, 1);       // (8, 128)
    gemm_tf32<false,false,false><<<gq, blk>>>(x, Wq, Q,  M, DIM, DIM, 0, 0, 0);
    gemm_tf32<false,false,false><<<gq, blk>>>(x, Wk, Kp, M, DIM, DIM, 0, 0, 0);
    gemm_tf32<false,false,false><<<gq, blk>>>(x, Wv, V,  M, DIM, DIM, 0, 0, 0);

    // S = Q K^T, causal tiles only
    dim3 gs(SEQ / BN, SEQ / BM, BATCH); // (16, 16, 8)
    gemm_tf32<true,true,false><<<gs, blk>>>(Q, Kp, S, SEQ, SEQ, DIM,
        (long)SEQ * DIM, (long)SEQ * DIM, (long)SEQ * SEQ);

    // softmax
    softmax_causal<<<dim3(SEQ, BATCH), 256>>>(S, SEQ);

    // O = P V with causal k-limit
    dim3 go(DIM / BN, SEQ / BM, BATCH); // (8, 16, 8)
    gemm_tf32<false,false,true><<<go, blk>>>(S, V, out, SEQ, DIM, SEQ,
        (long)SEQ * SEQ, (long)SEQ * DIM, (long)SEQ * DIM);
}

// round 12
// speedup vs baseline: 2.5765x; 1.0065x over previous
#include <cuda_runtime.h>
#include <cstdint>

// ---------------------------------------------------------------------------
// CausalAttention: B=8, N=2048, d_in=d_out=1024, fp32 in/out.
// All GEMMs on tensor pipe via mma.sync.m16n8k8 tf32 (fp32 accumulate).
//   Q = x Wq ; K = x Wk ; V = x Wv
//   S = Q K^T (causal tiles only) ; P = softmax(S/32) ; O = P V (k-limited)
// R10 delta vs R9 pass (1769us): vectorized nn-B staging (STS.128, kills 8-way
// bank conflict = 50% of L1 traffic in projections+PV); softmax zero-fill only
// to the 128-aligned tile boundary PV actually reads.
// ---------------------------------------------------------------------------

#define BATCH 8
#define SEQ   2048
#define DIM   1024

#define BM 128
#define BN 128
#define BK 16
#define PADL 136     // smem row length (floats): bank = (8k + m) % 32 -> conflict-free frags

__device__ float g_Q[(size_t)BATCH * SEQ * DIM];
__device__ float g_K[(size_t)BATCH * SEQ * DIM];
__device__ float g_V[(size_t)BATCH * SEQ * DIM];
__device__ float g_S[(size_t)BATCH * SEQ * SEQ];

__device__ __forceinline__ float to_tf32(float x) {
    float r;
    asm("cvt.rna.tf32.f32 %0, %1;" : "=f"(r) : "f"(x));
    return r;
}

__device__ __forceinline__ void mma_tf32(float c[4], const uint32_t a[4], const uint32_t b[2]) {
    asm volatile(
        "mma.sync.aligned.m16n8k8.row.col.f32.tf32.tf32.f32 "
        "{%0,%1,%2,%3}, {%4,%5,%6,%7}, {%8,%9}, {%0,%1,%2,%3};"
        : "+f"(c[0]), "+f"(c[1]), "+f"(c[2]), "+f"(c[3])
        : "r"(a[0]), "r"(a[1]), "r"(a[2]), "r"(a[3]), "r"(b[0]), "r"(b[1]));
}

// ---------------------------------------------------------------------------
// C[M,N] = A[M,K] * B  where B is [K,N] (TRANS_B=false) or [N,K] (TRANS_B=true,
// i.e. C = A * B^T). Batched via blockIdx.z with element strides.
// CAUSAL_SKIP: skip block tiles with bj > bi (upper triangle).
// CAUSAL_KLIM: limit k loop to (bi+1)*BM (P is lower-triangular).
// ---------------------------------------------------------------------------
template <bool TRANS_B, bool CAUSAL_SKIP, bool CAUSAL_KLIM>
__global__ __launch_bounds__(256)
void gemm_tf32(const float* __restrict__ A, const float* __restrict__ B,
               float* __restrict__ C, int M, int N, int K,
               long sA, long sB, long sC)
{
    const int bi = blockIdx.y;
    const int bj = blockIdx.x;
    if (CAUSAL_SKIP && bj > bi) return;

    __shared__ __align__(16) float As[2][BK][PADL];   // [k][m], padded
    __shared__ __align__(16) float Bs[2][BK][PADL];   // [k][n], padded

    const int b = blockIdx.z;
    A += (long)b * sA;
    B += (long)b * sB;
    C += (long)b * sC;

    const int tid  = threadIdx.x;
    const int lane = tid & 31;
    const int wid  = tid >> 5;
    const int wm = (wid & 1) * 64;    // warp row offset in block tile
    const int wn = (wid >> 1) * 32;   // warp col offset
    const int g  = lane >> 2;         // group id 0..7
    const int tg = lane & 3;          // thread-in-group 0..3

    const int kend = CAUSAL_KLIM ? min(K, (bi + 1) * BM) : K;
    const int T = kend / BK;

    // gmem->reg staging mappings
    const int aRow = tid >> 1;            // 0..127
    const int aK   = (tid & 1) * 8;       // 0 or 8
    const int bK   = tid >> 4;            // 0..15  (nn)
    const int bN   = (tid & 15) * 8;      // 0..120 (nn)
    // nt mode uses aRow/aK-style mapping for B (rows = n index, cols = k)
    const int nRow = tid >> 1;
    const int nK   = (tid & 1) * 8;

    float regA[8], regB[8];
    float acc[4][4][4] = {};

    // ---- gmem load of tile at k0 into registers ----
    auto load_gmem = [&](int k0) {
        const float4 a0 = *reinterpret_cast<const float4*>(
            A + (long)(bi * BM + aRow) * K + k0 + aK);
        const float4 a1 = *reinterpret_cast<const float4*>(
            A + (long)(bi * BM + aRow) * K + k0 + aK + 4);
        regA[0]=a0.x; regA[1]=a0.y; regA[2]=a0.z; regA[3]=a0.w;
        regA[4]=a1.x; regA[5]=a1.y; regA[6]=a1.z; regA[7]=a1.w;
        if (TRANS_B) {
            const float4 b0 = *reinterpret_cast<const float4*>(
                B + (long)(bj * BN + nRow) * K + k0 + nK);
            const float4 b1 = *reinterpret_cast<const float4*>(
                B + (long)(bj * BN + nRow) * K + k0 + nK + 4);
            regB[0]=b0.x; regB[1]=b0.y; regB[2]=b0.z; regB[3]=b0.w;
            regB[4]=b1.x; regB[5]=b1.y; regB[6]=b1.z; regB[7]=b1.w;
        } else {
            const float4 b0 = *reinterpret_cast<const float4*>(
                B + (long)(k0 + bK) * N + bj * BN + bN);
            const float4 b1 = *reinterpret_cast<const float4*>(
                B + (long)(k0 + bK) * N + bj * BN + bN + 4);
            regB[0]=b0.x; regB[1]=b0.y; regB[2]=b0.z; regB[3]=b0.w;
            regB[4]=b1.x; regB[5]=b1.y; regB[6]=b1.z; regB[7]=b1.w;
        }
    };

    // ---- regs -> smem (with tf32 rounding) ----
    auto stage = [&](int buf) {
        #pragma unroll
        for (int i = 0; i < 8; i++)
            As[buf][aK + i][aRow] = to_tf32(regA[i]);
        if (TRANS_B) {
            #pragma unroll
            for (int i = 0; i < 8; i++)
                Bs[buf][nK + i][nRow] = to_tf32(regB[i]);
        } else {
            // thread holds 8 CONSECUTIVE n for one k -> two STS.128
            // (scalar stores here were 8-way bank conflicted: bank == i mod 8
            //  for all 16 column lanes; vectorized = residual 2-way only)
            float4 v0 = make_float4(to_tf32(regB[0]), to_tf32(regB[1]),
                                    to_tf32(regB[2]), to_tf32(regB[3]));
            float4 v1 = make_float4(to_tf32(regB[4]), to_tf32(regB[5]),
                                    to_tf32(regB[6]), to_tf32(regB[7]));
            *reinterpret_cast<float4*>(&Bs[buf][bK][bN])     = v0;
            *reinterpret_cast<float4*>(&Bs[buf][bK][bN + 4]) = v1;
        }
    };

    // ---- mma over one BK=16 smem tile ----
    auto compute = [&](int buf) {
        #pragma unroll
        for (int s = 0; s < 2; s++) {
            uint32_t af[4][4], bf[4][2];
            #pragma unroll
            for (int mt = 0; mt < 4; mt++) {
                const int rb = wm + mt * 16;
                af[mt][0] = __float_as_uint(As[buf][s*8 + tg    ][rb + g    ]);
                af[mt][1] = __float_as_uint(As[buf][s*8 + tg    ][rb + g + 8]);
                af[mt][2] = __float_as_uint(As[buf][s*8 + tg + 4][rb + g    ]);
                af[mt][3] = __float_as_uint(As[buf][s*8 + tg + 4][rb + g + 8]);
            }
            #pragma unroll
            for (int nt = 0; nt < 4; nt++) {
                const int cb = wn + nt * 8;
                bf[nt][0] = __float_as_uint(Bs[buf][s*8 + tg    ][cb + g]);
                bf[nt][1] = __float_as_uint(Bs[buf][s*8 + tg + 4][cb + g]);
            }
            #pragma unroll
            for (int mt = 0; mt < 4; mt++)
                #pragma unroll
                for (int nt = 0; nt < 4; nt++)
                    mma_tf32(acc[mt][nt], af[mt], bf[nt]);
        }
    };

    // ---- pipelined main loop ----
    load_gmem(0);
    stage(0);
    __syncthreads();

    for (int t = 0; t < T; t++) {
        const int cur = t & 1;
        const bool more = (t + 1) < T;
        if (more) load_gmem((t + 1) * BK);
        compute(cur);
        if (more) {
            stage(cur ^ 1);
            __syncthreads();
        }
    }

    // ---- epilogue ----
    #pragma unroll
    for (int mt = 0; mt < 4; mt++) {
        #pragma unroll
        for (int nt = 0; nt < 4; nt++) {
            const int row = bi * BM + wm + mt * 16 + g;
            const int col = bj * BN + wn + nt * 8 + tg * 2;
            float* p = C + (long)row * N + col;
            *reinterpret_cast<float2*>(p) =
                make_float2(acc[mt][nt][0], acc[mt][nt][1]);
            *reinterpret_cast<float2*>(p + 8L * N) =
                make_float2(acc[mt][nt][2], acc[mt][nt][3]);
        }
    }
}

// ---------------------------------------------------------------------------
// Causal softmax in place: row n of batch b, valid entries m in [0, n],
// scale = 1/32. Zeros written only up to the 128-aligned tile boundary,
// which is all the PV GEMM (k-limit = ((n>>7)+1)<<7) ever reads.
// ---------------------------------------------------------------------------
__global__ __launch_bounds__(256)
void softmax_causal(float* __restrict__ S, int N)
{
    const int n = blockIdx.x;
    const int b = blockIdx.y;
    float* row = S + ((long)b * N + n) * N;
    const int tid = threadIdx.x;
    const float scale = 0.03125f;   // 1/32

    __shared__ float red[256];

    float m = -3.4e38f;
    for (int j = tid; j <= n; j += 256) m = fmaxf(m, row[j]);
    red[tid] = m;
    __syncthreads();
    for (int s = 128; s > 0; s >>= 1) {
        if (tid < s) red[tid] = fmaxf(red[tid], red[tid + s]);
        __syncthreads();
    }
    const float rowmax = red[0] * scale;
    __syncthreads();

    float sum = 0.f;
    for (int j = tid; j <= n; j += 256) {
        float p = __expf(row[j] * scale - rowmax);
        row[j] = p;
        sum += p;
    }
    red[tid] = sum;
    __syncthreads();
    for (int s = 128; s > 0; s >>= 1) {
        if (tid < s) red[tid] += red[tid + s];
        __syncthreads();
    }
    const float inv = 1.0f / red[0];
    __syncthreads();

    for (int j = tid; j <= n; j += 256) row[j] *= inv;
    const int zlim = ((n >> 7) + 1) << 7;   // PV reads only up to this tile edge
    for (int j = n + 1 + tid; j < zlim; j += 256) row[j] = 0.f;
}

// ---------------------------------------------------------------------------
extern "C" void kernel_launch(void* const* d_in, const int* in_sizes, int n_in,
                              void* d_out, int out_size)
{
    const float* x  = (const float*)d_in[0];
    const float* Wq = (const float*)d_in[1];
    const float* Wk = (const float*)d_in[2];
    const float* Wv = (const float*)d_in[3];
    float* out = (float*)d_out;

    float *Q, *Kp, *V, *S;
    cudaGetSymbolAddress((void**)&Q,  g_Q);
    cudaGetSymbolAddress((void**)&Kp, g_K);
    cudaGetSymbolAddress((void**)&V,  g_V);
    cudaGetSymbolAddress((void**)&S,  g_S);

    const dim3 blk(256);
    const int M = BATCH * SEQ;          // 16384

    // QKV projections: [16384,1024] x [1024,1024]
    dim3 gq(DIM / BN, M / BM, 1);       // (8, 128)
    gemm_tf32<false,false,false><<<gq, blk>>>(x, Wq, Q,  M, DIM, DIM, 0, 0, 0);
    gemm_tf32<false,false,false><<<gq, blk>>>(x, Wk, Kp, M, DIM, DIM, 0, 0, 0);
    gemm_tf32<false,false,false><<<gq, blk>>>(x, Wv, V,  M, DIM, DIM, 0, 0, 0);

    // S = Q K^T, causal tiles only
    dim3 gs(SEQ / BN, SEQ / BM, BATCH); // (16, 16, 8)
    gemm_tf32<true,true,false><<<gs, blk>>>(Q, Kp, S, SEQ, SEQ, DIM,
        (long)SEQ * DIM, (long)SEQ * DIM, (long)SEQ * SEQ);

    // softmax
    softmax_causal<<<dim3(SEQ, BATCH), 256>>>(S, SEQ);

    // O = P V with causal k-limit
    dim3 go(DIM / BN, SEQ / BM, BATCH); // (8, 16, 8)
    gemm_tf32<false,false,true><<<go, blk>>>(S, V, out, SEQ, DIM, SEQ,
        (long)SEQ * SEQ, (long)SEQ * DIM, (long)SEQ * DIM);
}